// round 4
// baseline (speedup 1.0000x reference)
#include <cuda_runtime.h>
#include <math.h>
#include <stdint.h>

// ---------------- problem constants ----------------
#define B_    64
#define TA    2048
#define FT    256
#define H_    1024
#define H4_   4096
#define CLS   96
#define EMB   256
#define TC    200

#define NCTA  128
#define NTHR  256
#define CHK   64          // k-rows per staged chunk
#define NCH   20          // 4 chunks of x/emb (256 k) + 16 chunks of h (1024 k)

// ---------------- smem layout (floats) ----------------
#define SM_WU   0                         // Wu[k][32], k in [0,1280): 40960 floats
#define SM_HC   (1280 * 32)               // 2 x [64][128] dup'd activation bufs
#define SM_MISC (SM_HC + 2 * CHK * 128)   // tokens (64 ints) + misc
#define SM_FLOATS (SM_MISC + 128)
#define SMEM_BYTES (SM_FLOATS * 4)        // 229,888 B

// ---------------- device globals (small!) ----------------
__device__ float g_hdup[2][H_ * 2 * B_];       // ping-pong h, [j][2b] duplicated (1MB)
__device__ float g_hplain[B_ * H_];            // plain h for fc (decoder)
__device__ int          g_pred[B_];
__device__ unsigned int g_bar = 0;

// ---------------- helpers ----------------
__device__ __forceinline__ uint64_t ffma2(uint64_t a, uint64_t b, uint64_t c) {
    uint64_t d;
    asm("fma.rn.f32x2 %0, %1, %2, %3;" : "=l"(d) : "l"(a), "l"(b), "l"(c));
    return d;
}
__device__ __forceinline__ uint64_t packf2(float lo, float hi) {
    uint64_t d;
    asm("mov.b64 %0, {%1, %2};" : "=l"(d) : "f"(lo), "f"(hi));
    return d;
}
__device__ __forceinline__ float sigm_(float x) { return 1.0f / (1.0f + expf(-x)); }

#define CP_COMMIT() asm volatile("cp.async.commit_group;" ::: "memory")
#define CP_WAIT1()  asm volatile("cp.async.wait_group 1;" ::: "memory")
#define CP_WAIT0()  asm volatile("cp.async.wait_group 0;" ::: "memory")

// 32KB contiguous global -> smem copy, 8 x 16B cp.async per thread
__device__ __forceinline__ void stage_cp(uint32_t smem_dst, const float* gsrc, int tid) {
#pragma unroll
    for (int i = 0; i < 8; i++) {
        uint32_t off = (uint32_t)(i * NTHR + tid) * 16u;
        asm volatile("cp.async.cg.shared.global [%0], [%1], 16;"
                     :: "r"(smem_dst + off), "l"((const char*)gsrc + off) : "memory");
    }
}

// scatter 16 prefetched x values (one chunk slice) into dup'd layout [64k][2b]
__device__ __forceinline__ void sts_dup(float* dst, const float4* v, int tid) {
    int b  = tid & 63;
    int kq = tid >> 6;                         // 0..3, 16 k each
    float* dp = dst + (kq * 16) * 128 + 2 * b;
#pragma unroll
    for (int m = 0; m < 4; m++) {
        float4 w = v[m];
        *(float2*)&dp[(m * 4 + 0) * 128] = make_float2(w.x, w.x);
        *(float2*)&dp[(m * 4 + 1) * 128] = make_float2(w.y, w.y);
        *(float2*)&dp[(m * 4 + 2) * 128] = make_float2(w.z, w.z);
        *(float2*)&dp[(m * 4 + 3) * 128] = make_float2(w.w, w.w);
    }
}

// embedding gather -> dup'd smem chunk (decoder chunks 0..3)
__device__ __forceinline__ void stage_emb(float* dst, const float* __restrict__ embed,
                                          const int* tok_s, int c, int tid) {
    int b  = tid & 63;
    int kq = tid >> 6;
    int tok = tok_s[b];
    const float* er = embed + (size_t)tok * EMB + c * CHK + kq * 16;
    float4 v[4];
#pragma unroll
    for (int m = 0; m < 4; m++) v[m] = *(const float4*)(er + m * 4);
    sts_dup(dst, v, tid);
}

// Monotonic-ticket grid barrier (graph-replay safe).
__device__ __forceinline__ void grid_sync_() {
    __threadfence();
    __syncthreads();
    if (threadIdx.x == 0) {
        unsigned int my   = atomicAdd(&g_bar, 1u);
        unsigned int goal = my - (my % NCTA) + NCTA;
        for (;;) {
            unsigned int v = *(volatile unsigned int*)&g_bar;
            if ((int)(v - goal) >= 0) break;
            __nanosleep(64);
        }
    }
    __threadfence();
    __syncthreads();
}

// inner FFMA2 loop over one 64-k chunk
__device__ __forceinline__ void compute_chunk(const float* __restrict__ hcb,
                                              const float* __restrict__ WU, int kg0,
                                              int hoff, int uoff,
                                              uint64_t& a00, uint64_t& a01,
                                              uint64_t& a10, uint64_t& a11) {
    const float* hp = hcb + hoff;
    const float* up = WU + kg0 * 32 + uoff;
#pragma unroll 16
    for (int k = 0; k < CHK; k++) {
        ulonglong2 hv = *(const ulonglong2*)(hp + k * 128);  // (hb,hb),(hb1,hb1)
        ulonglong2 uv = *(const ulonglong2*)(up + k * 32);   // (uc0,uc1),(uc2,uc3)
        a00 = ffma2(hv.x, uv.x, a00);
        a01 = ffma2(hv.x, uv.y, a01);
        a10 = ffma2(hv.y, uv.x, a10);
        a11 = ffma2(hv.y, uv.y, a11);
    }
}

// ---------------- main persistent kernel ----------------
__global__ void __launch_bounds__(NTHR, 1)
lstm_persistent(const float* __restrict__ x,
                const float* __restrict__ encW, const float* __restrict__ encU,
                const float* __restrict__ encb,
                const float* __restrict__ embed,
                const float* __restrict__ decW, const float* __restrict__ decU,
                const float* __restrict__ decb,
                const float* __restrict__ fcW, const float* __restrict__ fcb,
                const int* __restrict__ sotp,
                float* __restrict__ outf, int* __restrict__ outi, int mode)
{
    extern __shared__ float sm[];
    float* WU   = sm + SM_WU;
    int*   tokS = (int*)(sm + SM_MISC);
    float* msc  = sm + SM_MISC + 96;

    const int tid  = threadIdx.x;
    const int cta  = blockIdx.x;
    const int warp = tid >> 5, lane = tid & 31;
    const int bg = warp & 3, cg = warp >> 2;       // 4 batch-groups x 2 col-groups
    const int bl = lane & 7, cl = lane >> 3;
    const int pairB = bg * 16 + bl * 2;            // batches pairB, pairB+1
    const int Cb    = cg * 16 + cl * 4;            // local cols Cb..Cb+3
    const int hoff  = pairB * 2;
    const int uoff  = Cb;

    const int xb = tid & 63, xkq = tid >> 6;       // x prefetch mapping

    uint32_t smem_u32 = (uint32_t)__cvta_generic_to_shared(sm);
    uint32_t hc_u32[2] = { smem_u32 + SM_HC * 4u, smem_u32 + (SM_HC + 8192) * 4u };
    float* hcb[2] = { sm + SM_HC, sm + SM_HC + 8192 };
    float* zs = sm + SM_HC;                        // z reuses buf0 (stride-34 rows)

    // ---- init: zero h0 (dup layout), load encoder weights transposed ----
    {
        float* h0 = g_hdup[0] + cta * 1024;
        for (int i = tid; i < 1024; i += NTHR) h0[i] = 0.0f;
    }
    for (int i = tid; i < 1280 * 32; i += NTHR) {
        int c = i & 31, k = i >> 5;
        int colg = (c >> 3) * H_ + cta * 8 + (c & 7);
        WU[k * 32 + c] = (k < FT) ? encW[(size_t)k * H4_ + colg]
                                  : encU[(size_t)(k - FT) * H4_ + colg];
    }
    uint64_t bias2_0, bias2_1;
    {
        auto cg_ = [&](int c) { return (c >> 3) * H_ + cta * 8 + (c & 7); };
        bias2_0 = packf2(encb[cg_(Cb)],     encb[cg_(Cb + 1)]);
        bias2_1 = packf2(encb[cg_(Cb + 2)], encb[cg_(Cb + 3)]);
    }
    __syncthreads();
    grid_sync_();

    float c0r = 0.0f, c1r = 0.0f;   // cell state for (b,j) pairs p=2*tid, 2*tid+1

    // =================== encoder: 2048 steps ===================
    for (int t = 0; t < TA; ++t) {
        const float* hsrc  = g_hdup[t & 1];
        float*       hdstd = g_hdup[(t + 1) & 1];

        // prefetch ALL x chunks of this step into registers (16 x LDG.128)
        float4 xr[4][4];
        {
            const float* xrow = x + (size_t)xb * (TA * FT) + (size_t)t * FT + xkq * 16;
#pragma unroll
            for (int c4 = 0; c4 < 4; c4++)
#pragma unroll
                for (int m = 0; m < 4; m++)
                    xr[c4][m] = *(const float4*)(xrow + c4 * CHK + m * 4);
        }

        uint64_t a00 = bias2_0, a01 = bias2_1, a10 = bias2_0, a11 = bias2_1;

        sts_dup(hcb[0], xr[0], tid);       // chunk 0 (stalls on first LDGs only)
        CP_COMMIT();
        for (int c = 0; c < NCH; ++c) {
            __syncthreads();               // buffer (c+1)&1 free of readers
            if (c + 1 < NCH) {
                if (c + 1 < 4) sts_dup(hcb[(c + 1) & 1], xr[c + 1], tid);
                else           stage_cp(hc_u32[(c + 1) & 1],
                                        hsrc + (c + 1 - 4) * CHK * 128, tid);
            }
            CP_COMMIT();
            if (c + 1 < NCH) CP_WAIT1(); else CP_WAIT0();
            __syncthreads();
            compute_chunk(hcb[c & 1], WU, c * CHK, hoff, uoff, a00, a01, a10, a11);
        }

        // z scatter (buf0 free: last chunk computed from buf1)
        *(uint64_t*)&zs[(pairB    ) * 34 + Cb    ] = a00;
        *(uint64_t*)&zs[(pairB    ) * 34 + Cb + 2] = a01;
        *(uint64_t*)&zs[(pairB + 1) * 34 + Cb    ] = a10;
        *(uint64_t*)&zs[(pairB + 1) * 34 + Cb + 2] = a11;
        __syncthreads();

#pragma unroll
        for (int q = 0; q < 2; ++q) {
            int pp = tid * 2 + q;
            int b = pp >> 3, j = pp & 7;
            float zi = zs[b * 34 +      j];
            float zf = zs[b * 34 +  8 + j];
            float zg = zs[b * 34 + 16 + j];
            float zo = zs[b * 34 + 24 + j];
            float ig = sigm_(zi), fg = sigm_(zf), gg = tanhf(zg), og = sigm_(zo);
            float& cr = q ? c1r : c0r;
            cr = fg * cr + ig * gg;
            float h = og * tanhf(cr);
            int jg = cta * 8 + j;
            *(float2*)&hdstd[jg * 128 + 2 * b] = make_float2(h, h);
        }
        grid_sync_();
    }

    // ---- swap to decoder weights ----
    for (int i = tid; i < 1280 * 32; i += NTHR) {
        int c = i & 31, k = i >> 5;
        int colg = (c >> 3) * H_ + cta * 8 + (c & 7);
        WU[k * 32 + c] = (k < EMB) ? decW[(size_t)k * H4_ + colg]
                                   : decU[(size_t)(k - EMB) * H4_ + colg];
    }
    {
        auto cg_ = [&](int c) { return (c >> 3) * H_ + cta * 8 + (c & 7); };
        bias2_0 = packf2(decb[cg_(Cb)],     decb[cg_(Cb + 1)]);
        bias2_1 = packf2(decb[cg_(Cb + 2)], decb[cg_(Cb + 3)]);
    }
    const int sotv = *sotp;
    __syncthreads();

    // =================== decoder: 200 steps ===================
    for (int s = 0; s < TC; ++s) {
        const float* hsrc  = g_hdup[s & 1];
        float*       hdstd = g_hdup[(s + 1) & 1];

        if (tid < B_) tokS[tid] = (s == 0) ? sotv : __ldcg(&g_pred[tid]);
        __syncthreads();

        uint64_t a00 = bias2_0, a01 = bias2_1, a10 = bias2_0, a11 = bias2_1;

        stage_emb(hcb[0], embed, tokS, 0, tid);
        CP_COMMIT();
        for (int c = 0; c < NCH; ++c) {
            __syncthreads();
            if (c + 1 < NCH) {
                if (c + 1 < 4) stage_emb(hcb[(c + 1) & 1], embed, tokS, c + 1, tid);
                else           stage_cp(hc_u32[(c + 1) & 1],
                                        hsrc + (c + 1 - 4) * CHK * 128, tid);
            }
            CP_COMMIT();
            if (c + 1 < NCH) CP_WAIT1(); else CP_WAIT0();
            __syncthreads();
            compute_chunk(hcb[c & 1], WU, c * CHK, hoff, uoff, a00, a01, a10, a11);
        }

        *(uint64_t*)&zs[(pairB    ) * 34 + Cb    ] = a00;
        *(uint64_t*)&zs[(pairB    ) * 34 + Cb + 2] = a01;
        *(uint64_t*)&zs[(pairB + 1) * 34 + Cb    ] = a10;
        *(uint64_t*)&zs[(pairB + 1) * 34 + Cb + 2] = a11;
        __syncthreads();

#pragma unroll
        for (int q = 0; q < 2; ++q) {
            int pp = tid * 2 + q;
            int b = pp >> 3, j = pp & 7;
            float zi = zs[b * 34 +      j];
            float zf = zs[b * 34 +  8 + j];
            float zg = zs[b * 34 + 16 + j];
            float zo = zs[b * 34 + 24 + j];
            float ig = sigm_(zi), fg = sigm_(zf), gg = tanhf(zg), og = sigm_(zo);
            float& cr = q ? c1r : c0r;
            cr = fg * cr + ig * gg;
            float h = og * tanhf(cr);
            int jg = cta * 8 + j;
            *(float2*)&hdstd[jg * 128 + 2 * b] = make_float2(h, h);
            g_hplain[b * H_ + jg] = h;
        }
        grid_sync_();   // h visible everywhere

        // ---- fc + softmax + argmax: CTA b handles batch row b ----
        if (cta < B_) {
            const int b = cta;
            float* hcf = hcb[1];             // dead chunk-19 buffer
            float* lg  = hcf + 1024 + 32;    // logits scratch
            for (int i = tid; i < H_ / 4; i += NTHR)
                *(float4*)&hcf[i * 4] = *(const float4*)&g_hplain[b * H_ + i * 4];
            __syncthreads();
            if (tid < CLS) {
                float a0 = 0.f, a1 = 0.f, a2 = 0.f, a3 = 0.f;
#pragma unroll 4
                for (int k = 0; k < H_; k += 4) {
                    a0 = fmaf(hcf[k + 0], __ldg(&fcW[(k + 0) * CLS + tid]), a0);
                    a1 = fmaf(hcf[k + 1], __ldg(&fcW[(k + 1) * CLS + tid]), a1);
                    a2 = fmaf(hcf[k + 2], __ldg(&fcW[(k + 2) * CLS + tid]), a2);
                    a3 = fmaf(hcf[k + 3], __ldg(&fcW[(k + 3) * CLS + tid]), a3);
                }
                lg[tid] = fcb[tid] + ((a0 + a1) + (a2 + a3));
            }
            __syncthreads();
            if (tid == 0) {
                float m = lg[0];
                for (int j = 1; j < CLS; ++j) m = fmaxf(m, lg[j]);
                float sum = 0.0f, best = -1.0f; int bi = 0;
                for (int j = 0; j < CLS; ++j) {
                    float e = expf(lg[j] - m);
                    lg[j] = e;
                    sum += e;
                    if (e > best) { best = e; bi = j; }   // first-max == jnp.argmax
                }
                msc[0] = sum;
                g_pred[b] = bi;
                if (mode == 0)      outf[(size_t)s * B_ + b] = (float)bi;
                else if (mode == 1) outi[(size_t)s * B_ + b] = bi;
            }
            __syncthreads();
            if (tid < CLS) {
                float pv = lg[tid] / msc[0];
                if (mode == 0)
                    outf[(size_t)TC * B_ + ((size_t)s * B_ + b) * CLS + tid] = pv;
                else if (mode == 2)
                    outf[((size_t)s * B_ + b) * CLS + tid] = pv;
            }
        }
        grid_sync_();   // preds visible for next step's embedding
    }
}

extern "C" void kernel_launch(void* const* d_in, const int* in_sizes, int n_in,
                              void* d_out, int out_size) {
    const float* x    = (const float*)d_in[0];
    const float* encW = (const float*)d_in[1];
    const float* encU = (const float*)d_in[2];
    const float* encb = (const float*)d_in[3];
    const float* emb  = (const float*)d_in[4];
    const float* decW = (const float*)d_in[5];
    const float* decU = (const float*)d_in[6];
    const float* decb = (const float*)d_in[7];
    const float* fcW  = (const float*)d_in[8];
    const float* fcb  = (const float*)d_in[9];
    const int*   sot  = (const int*)d_in[10];

    int mode = 0;                                   // both (floats), preds first
    if (out_size == TC * B_)            mode = 1;   // preds only (int32)
    else if (out_size == TC * B_ * CLS) mode = 2;   // probs only (float32)

    cudaFuncSetAttribute(lstm_persistent,
                         cudaFuncAttributeMaxDynamicSharedMemorySize, SMEM_BYTES);
    lstm_persistent<<<NCTA, NTHR, SMEM_BYTES>>>(
        x, encW, encU, encb, emb, decW, decU, decb, fcW, fcb, sot,
        (float*)d_out, (int*)d_out, mode);
}